// round 14
// baseline (speedup 1.0000x reference)
#include <cuda_runtime.h>
#include <cuda_fp16.h>
#include <math.h>
#include <stdint.h>

// Problem constants: B=2, T=2048, C=1024, H=16, D=64
#define TB   2
#define TT   2048
#define TC   1024
#define TH   16
#define TD   64
#define TM_  (TB*TT)          // 4096 rows total
#define C3   (3*TC)           // 3072
#define C4   (4*TC)           // 4096
#define BH   (TB*TH)          // 32

// ---------------------------------------------------------------------------
// Scratch (no allocations allowed -> __device__ globals)
// ---------------------------------------------------------------------------
__device__ __half g_h1  [TM_ * TC];       // ln1(x)              fp16
__device__ __half g_q   [BH * TT * TD];   // Q (scaled, log2e-folded) fp16 head-major
__device__ __half g_k   [BH * TT * TD];   // K                   fp16 head-major
__device__ __half g_v   [BH * TT * TD];   // V                   fp16 head-major
__device__ __half g_att [TM_ * TC];       // attention output    fp16
__device__ float  g_x1  [TM_ * TC];       // x + attn_proj       fp32
__device__ __half g_h2  [TM_ * TC];       // ln2(x1)             fp16
__device__ __half g_fc  [TM_ * C4];       // gelu(fc)            fp16
// fp16 copies of weights, SAME layout as input ([K][N] row-major)
__device__ __half g_wqkvH[TC * C3];
__device__ __half g_wapH [TC * TC];
__device__ __half g_wfcH [TC * C4];
__device__ __half g_woutH[C4 * TC];

// ---------------------------------------------------------------------------
// Helpers
// ---------------------------------------------------------------------------
__device__ __forceinline__ uint32_t h2u(__half2 h) {
    union { __half2 h; uint32_t u; } c;
    c.h = h;
    return c.u;
}
__device__ __forceinline__ float ex2f(float x) {   // 2^x, single MUFU op
    float r;
    asm("ex2.approx.ftz.f32 %0, %1;" : "=f"(r) : "f"(x));
    return r;
}
__device__ __forceinline__ uint32_t smem_u32(const void* p) {
    uint32_t a;
    asm("{ .reg .u64 t; cvta.to.shared.u64 t, %1; cvt.u32.u64 %0, t; }"
        : "=r"(a) : "l"(p));
    return a;
}
__device__ __forceinline__ void cp_async16(uint32_t dst, const void* src) {
    asm volatile("cp.async.cg.shared.global [%0], [%1], 16;"
                 :: "r"(dst), "l"(src) : "memory");
}
#define CP_COMMIT() asm volatile("cp.async.commit_group;" ::: "memory")
#define CP_WAIT1()  asm volatile("cp.async.wait_group 1;" ::: "memory")

__device__ __forceinline__ void mma_f16(float* d, const uint32_t* a, const uint32_t* b) {
    asm volatile(
        "mma.sync.aligned.m16n8k16.row.col.f32.f16.f16.f32 "
        "{%0,%1,%2,%3}, {%4,%5,%6,%7}, {%8,%9}, {%0,%1,%2,%3};"
        : "+f"(d[0]), "+f"(d[1]), "+f"(d[2]), "+f"(d[3])
        : "r"(a[0]), "r"(a[1]), "r"(a[2]), "r"(a[3]), "r"(b[0]), "r"(b[1]));
}
__device__ __forceinline__ void ldsm_x4(uint32_t* r, uint32_t addr) {
    asm volatile("ldmatrix.sync.aligned.m8n8.x4.shared.b16 {%0,%1,%2,%3}, [%4];"
                 : "=r"(r[0]), "=r"(r[1]), "=r"(r[2]), "=r"(r[3]) : "r"(addr));
}
__device__ __forceinline__ void ldsm_x4_t(uint32_t* r, uint32_t addr) {
    asm volatile("ldmatrix.sync.aligned.m8n8.x4.trans.shared.b16 {%0,%1,%2,%3}, [%4];"
                 : "=r"(r[0]), "=r"(r[1]), "=r"(r[2]), "=r"(r[3]) : "r"(addr));
}

// ---------------------------------------------------------------------------
// Fused fp32 -> fp16 convert for ALL four weight matrices, one launch.
// ---------------------------------------------------------------------------
#define CVT_N1 (TC * C3)
#define CVT_N2 (TC * TC)
#define CVT_N3 (TC * C4)
#define CVT_N4 (C4 * TC)
#define CVT_TOT (CVT_N1 + CVT_N2 + CVT_N3 + CVT_N4)

__global__ __launch_bounds__(256) void convert_all_kernel(
    const float* __restrict__ w1, const float* __restrict__ w2,
    const float* __restrict__ w3, const float* __restrict__ w4,
    __half* __restrict__ o1, __half* __restrict__ o2,
    __half* __restrict__ o3, __half* __restrict__ o4)
{
    int i = (blockIdx.x * 256 + threadIdx.x) * 8;
    if (i >= CVT_TOT) return;
    const float* W;
    __half* Wh;
    if (i < CVT_N1)                       { W = w1;  Wh = o1;  }
    else if (i < CVT_N1 + CVT_N2)         { W = w2 - CVT_N1;           Wh = o2 - CVT_N1; }
    else if (i < CVT_N1 + CVT_N2 + CVT_N3){ W = w3 - CVT_N1 - CVT_N2;  Wh = o3 - CVT_N1 - CVT_N2; }
    else                                  { W = w4 - CVT_N1 - CVT_N2 - CVT_N3; Wh = o4 - CVT_N1 - CVT_N2 - CVT_N3; }
    float4 a = *reinterpret_cast<const float4*>(W + i);
    float4 b = *reinterpret_cast<const float4*>(W + i + 4);
    __half2 h[4];
    h[0] = __floats2half2_rn(a.x, a.y);
    h[1] = __floats2half2_rn(a.z, a.w);
    h[2] = __floats2half2_rn(b.x, b.y);
    h[3] = __floats2half2_rn(b.z, b.w);
    *reinterpret_cast<uint4*>(Wh + i) = *reinterpret_cast<uint4*>(h);
}

// ---------------------------------------------------------------------------
// fp16 tensor GEMM (at legacy-HMMA ceiling — do not touch)
// BM=128, BN=128, BK=64. 256 threads = 8 warps (4m x 2n); warp tile 32x64.
// ---------------------------------------------------------------------------
#define A_BYTES   (128 * 144)
#define B_BYTES   (64 * 272)
#define STG_BYTES (A_BYTES + B_BYTES)    // 35840
#define GNST      3
#define G_SMEM    (GNST * STG_BYTES)     // 107520

template <int EPI, typename OutT>
__global__ __launch_bounds__(256) void hgemm(
    const __half* __restrict__ A, const __half* __restrict__ W,
    const float* __restrict__ bias, const float* __restrict__ res,
    OutT* __restrict__ C,
    __half* __restrict__ qh, __half* __restrict__ kh, __half* __restrict__ vh,
    int M, int N, int K)
{
    extern __shared__ __half shh[];
    uint32_t sbase = smem_u32(shh);

    int tid  = threadIdx.x;
    int wid  = tid >> 5;
    int lane = tid & 31;
    int g    = lane >> 2;
    int t    = lane & 3;
    int brow = blockIdx.y * 128;
    int bcol = blockIdx.x * 128;
    int m0   = (wid >> 1) * 32;
    int n0   = (wid & 1) * 64;

    const __half* Ag = A + (size_t)brow * K;

    int NC = K >> 6;

    auto issue = [&](int kc) {
        if (kc < NC) {
            int k0 = kc << 6;
            uint32_t abuf = sbase + (uint32_t)(kc % GNST) * STG_BYTES;
            uint32_t bbuf = abuf + A_BYTES;
            #pragma unroll
            for (int i = 0; i < 4; i++) {               // A: 1024 x 16B
                int idx = tid + (i << 8);
                int row = idx >> 3;
                int c   = idx & 7;
                cp_async16(abuf + (uint32_t)(row * 144 + c * 16),
                           Ag + (size_t)row * K + k0 + c * 8);
            }
            #pragma unroll
            for (int i = 0; i < 4; i++) {               // B: 1024 x 16B
                int idx = tid + (i << 8);
                int row = idx >> 4;
                int c   = idx & 15;
                cp_async16(bbuf + (uint32_t)(row * 272 + c * 16),
                           W + (size_t)(k0 + row) * N + bcol + c * 8);
            }
        }
        CP_COMMIT();
    };

    float acc[2][8][4];
    #pragma unroll
    for (int i = 0; i < 2; i++)
        #pragma unroll
        for (int j = 0; j < 8; j++)
            #pragma unroll
            for (int q = 0; q < 4; q++) acc[i][j][q] = 0.f;

    issue(0);
    issue(1);

    int a_r = lane & 15;
    int a_c = (lane >> 4) * 16;
    int b_tr = ((lane >> 3) & 1) * 8 + (lane & 7);
    int b_tc = ((lane >> 4) & 1) * 16;

    for (int kc = 0; kc < NC; kc++) {
        CP_WAIT1();
        __syncthreads();
        issue(kc + 2);

        uint32_t As = sbase + (uint32_t)(kc % GNST) * STG_BYTES;
        uint32_t Bs = As + A_BYTES;

        #pragma unroll
        for (int ks = 0; ks < 4; ks++) {
            uint32_t a[2][4];
            #pragma unroll
            for (int i = 0; i < 2; i++)
                ldsm_x4(a[i], As + (uint32_t)((m0 + i * 16 + a_r) * 144 + ks * 32 + a_c));
            uint32_t b[4][4];
            #pragma unroll
            for (int jp = 0; jp < 4; jp++)
                ldsm_x4_t(b[jp], Bs + (uint32_t)((ks * 16 + b_tr) * 272
                                                 + n0 * 2 + jp * 32 + b_tc));
            #pragma unroll
            for (int i = 0; i < 2; i++)
                #pragma unroll
                for (int j = 0; j < 8; j++)
                    mma_f16(acc[i][j], a[i], b[j >> 1] + (j & 1) * 2);
        }
    }

    // ---- epilogue ----
    #pragma unroll
    for (int i = 0; i < 2; i++) {
        int r0 = brow + m0 + i * 16 + g;
        int r1 = r0 + 8;
        #pragma unroll
        for (int j = 0; j < 8; j++) {
            int c0 = bcol + n0 + j * 8 + 2 * t;
            float bx = bias[c0], by = bias[c0 + 1];
            float v0 = acc[i][j][0] + bx;
            float v1 = acc[i][j][1] + by;
            float v2 = acc[i][j][2] + bx;
            float v3 = acc[i][j][3] + by;
            if (EPI == 1) {
                v0 = 0.5f * v0 * (1.0f + erff(v0 * 0.70710678118654752440f));
                v1 = 0.5f * v1 * (1.0f + erff(v1 * 0.70710678118654752440f));
                v2 = 0.5f * v2 * (1.0f + erff(v2 * 0.70710678118654752440f));
                v3 = 0.5f * v3 * (1.0f + erff(v3 * 0.70710678118654752440f));
            } else if (EPI == 2) {
                const float2 ra = *reinterpret_cast<const float2*>(res + (size_t)r0 * N + c0);
                const float2 rb = *reinterpret_cast<const float2*>(res + (size_t)r1 * N + c0);
                v0 += ra.x; v1 += ra.y; v2 += rb.x; v3 += rb.y;
            }
            if (EPI == 3) {
                // scatter into head-major Q/K/V.
                // Q scale folds C^-0.5 AND log2(e): softmax runs in log2 domain.
                int which = c0 >> 10;
                int cc = c0 & 1023;
                int hh = cc >> 6, d = cc & 63;
                __half* base = (which == 0) ? qh : ((which == 1) ? kh : vh);
                float s = (which == 0) ? 0.045084220027780106f : 1.0f; // 2^-5 * log2(e)
                int b0i = r0 >> 11, t0i = r0 & 2047;
                int b1i = r1 >> 11, t1i = r1 & 2047;
                *reinterpret_cast<__half2*>(base + ((size_t)((b0i * TH + hh) * TT + t0i) * TD + d)) =
                    __floats2half2_rn(v0 * s, v1 * s);
                *reinterpret_cast<__half2*>(base + ((size_t)((b1i * TH + hh) * TT + t1i) * TD + d)) =
                    __floats2half2_rn(v2 * s, v3 * s);
            } else if constexpr (sizeof(OutT) == 2) {
                *reinterpret_cast<__half2*>((__half*)C + (size_t)r0 * N + c0) = __floats2half2_rn(v0, v1);
                *reinterpret_cast<__half2*>((__half*)C + (size_t)r1 * N + c0) = __floats2half2_rn(v2, v3);
            } else {
                *reinterpret_cast<float2*>((float*)C + (size_t)r0 * N + c0) = make_float2(v0, v1);
                *reinterpret_cast<float2*>((float*)C + (size_t)r1 * N + c0) = make_float2(v2, v3);
            }
        }
    }
}

// ---------------------------------------------------------------------------
// Block reduce (for LayerNorm)
// ---------------------------------------------------------------------------
__device__ __forceinline__ float blockReduceSum(float v) {
    __shared__ float sh[32];
    int lane = threadIdx.x & 31;
    #pragma unroll
    for (int o = 16; o > 0; o >>= 1) v += __shfl_xor_sync(0xffffffffu, v, o);
    __syncthreads();
    if (lane == 0) sh[threadIdx.x >> 5] = v;
    __syncthreads();
    float t = (lane < 8) ? sh[lane] : 0.f;
    #pragma unroll
    for (int o = 4; o > 0; o >>= 1) t += __shfl_xor_sync(0xffffffffu, t, o);
    return __shfl_sync(0xffffffffu, t, 0);
}

// ---------------------------------------------------------------------------
// LayerNorm -> fp16
// ---------------------------------------------------------------------------
__global__ __launch_bounds__(256) void layernorm_kernel(
    const float* __restrict__ x, const float* __restrict__ g,
    const float* __restrict__ b, __half* __restrict__ out)
{
    int row = blockIdx.x;
    const float4* xr = reinterpret_cast<const float4*>(x + (size_t)row * TC);
    float4 v = xr[threadIdx.x];
    float mean = blockReduceSum(v.x + v.y + v.z + v.w) * (1.f / TC);
    float dx = v.x - mean, dy = v.y - mean, dz = v.z - mean, dw = v.w - mean;
    float var = blockReduceSum(dx*dx + dy*dy + dz*dz + dw*dw) * (1.f / TC);
    float rstd = rsqrtf(var + 1e-5f);
    float4 gv = reinterpret_cast<const float4*>(g)[threadIdx.x];
    float4 bv = reinterpret_cast<const float4*>(b)[threadIdx.x];
    __half2* o2 = reinterpret_cast<__half2*>(out + (size_t)row * TC);
    o2[2 * threadIdx.x]     = __floats2half2_rn(dx * rstd * gv.x + bv.x, dy * rstd * gv.y + bv.y);
    o2[2 * threadIdx.x + 1] = __floats2half2_rn(dz * rstd * gv.z + bv.z, dw * rstd * gv.w + bv.w);
}

// ---------------------------------------------------------------------------
// Causal flash attention — R13 loop (3 KV buffers, ONE sync/tile) with
// OCCUPANCY target 3 CTAs/SM: Qa fragments reloaded from smem each tile
// (frees 16 persistent regs; Qs is smem-resident anyway) and
// __launch_bounds__(256, 3) to cap regs at 84. smem 73.7KB x 3 = 221KB fits.
// ---------------------------------------------------------------------------
#define AST    72
#define QS_H   (128 * AST)      // 9216 halfs
#define KS_H   (64 * AST)       // 4608 halfs
#define ATT_SMEM ((QS_H + 6 * KS_H) * 2)  // 73728 bytes

__global__ __launch_bounds__(256, 3) void attn_kernel(
    const __half* __restrict__ Qh, const __half* __restrict__ Kh,
    const __half* __restrict__ Vh, __half* __restrict__ out)
{
    extern __shared__ __half ash[];
    __half* Qs  = ash;
    __half* KsB = ash + QS_H;            // 3 x KS_H
    __half* VsB = ash + QS_H + 3 * KS_H; // 3 x KS_H

    int qt  = gridDim.x - 1 - blockIdx.x;   // heavy (large-qt) CTAs first
    int bh  = blockIdx.y;                   // b*16 + h
    int tid = threadIdx.x;
    int wid = tid >> 5;
    int lane = tid & 31;
    int g = lane >> 2;
    int t = lane & 3;
    int qr = wid * 16;                   // local q row base (0..112)

    // ---- stage Q supertile (128 x 64, pre-scaled fp16) ----
    const __half* qbase = Qh + ((size_t)bh * TT + qt * 128) * TD;
    #pragma unroll
    for (int i = 0; i < 4; i++) {
        int idx = tid + (i << 8);            // 0..1023
        int r = idx >> 3, c = idx & 7;
        *reinterpret_cast<uint4*>(Qs + r * AST + c * 8) =
            *reinterpret_cast<const uint4*>(qbase + r * TD + c * 8);
    }
    __syncthreads();

    uint32_t sQ = smem_u32(Qs);
    uint32_t qaddr = sQ + (uint32_t)((qr + (lane & 15)) * AST + (lane >> 4) * 8) * 2;

    float O[8][4];
    #pragma unroll
    for (int j = 0; j < 8; j++)
        #pragma unroll
        for (int q = 0; q < 4; q++) O[j][q] = 0.f;
    float mrow[2] = {-1e30f, -1e30f};
    float lrow[2] = {0.f, 0.f};

    int ktmax = 2 * qt + 1;              // last kv tile index

    auto issueKV = [&](int kt) {
        if (kt <= ktmax) {
            const __half* kbase = Kh + ((size_t)bh * TT + kt * 64) * TD;
            const __half* vbase = Vh + ((size_t)bh * TT + kt * 64) * TD;
            uint32_t kb = smem_u32(KsB + (kt % 3) * KS_H);
            uint32_t vb = smem_u32(VsB + (kt % 3) * KS_H);
            #pragma unroll
            for (int i = 0; i < 2; i++) {
                int idx = tid + (i << 8);    // 0..511
                int r = idx >> 3, c = idx & 7;
                uint32_t so = (uint32_t)(r * AST + c * 8) * 2;
                cp_async16(kb + so, kbase + r * TD + c * 8);
                cp_async16(vb + so, vbase + r * TD + c * 8);
            }
        }
        CP_COMMIT();
    };

    issueKV(0);
    issueKV(1);

    for (int kt = 0; kt <= ktmax; kt++) {
        CP_WAIT1();            // tile kt resident (only kt+1 may be pending)
        __syncthreads();       // + all warps done with iter kt-1 reads
        uint32_t sK = smem_u32(KsB + (kt % 3) * KS_H);
        uint32_t sV = smem_u32(VsB + (kt % 3) * KS_H);

        // ---- S = Q @ K^T  (Qa reloaded per k-step from smem) ----
        float S[8][4];
        #pragma unroll
        for (int jp = 0; jp < 4; jp++) {
            #pragma unroll
            for (int q = 0; q < 4; q++) { S[2*jp][q] = 0.f; S[2*jp+1][q] = 0.f; }
        }
        #pragma unroll
        for (int ks = 0; ks < 4; ks++) {
            uint32_t Qa[4];
            ldsm_x4(Qa, qaddr + (uint32_t)(ks * 16) * 2);
            #pragma unroll
            for (int jp = 0; jp < 4; jp++) {
                uint32_t kb4[4];
                ldsm_x4(kb4, sK + (uint32_t)((jp * 16 + ((lane >> 4) & 1) * 8 + (lane & 7)) * AST
                                             + ks * 16 + ((lane >> 3) & 1) * 8) * 2);
                mma_f16(S[2*jp],     Qa, kb4);
                mma_f16(S[2*jp + 1], Qa, kb4 + 2);
            }
        }

        // ---- causal mask (last two kv tiles interact with the diagonal) ----
        if (kt >= 2 * qt) {
            int off = (kt - 2 * qt) * 64;
            int r0 = qr + g, r1 = r0 + 8;
            #pragma unroll
            for (int j = 0; j < 8; j++) {
                int c0 = off + 8 * j + 2 * t, c1 = c0 + 1;
                if (c0 > r0) S[j][0] = -1e30f;
                if (c1 > r0) S[j][1] = -1e30f;
                if (c0 > r1) S[j][2] = -1e30f;
                if (c1 > r1) S[j][3] = -1e30f;
            }
        }

        // ---- online softmax (base 2) ----
        float mx0 = -1e30f, mx1 = -1e30f;
        #pragma unroll
        for (int j = 0; j < 8; j++) {
            mx0 = fmaxf(mx0, fmaxf(S[j][0], S[j][1]));
            mx1 = fmaxf(mx1, fmaxf(S[j][2], S[j][3]));
        }
        #pragma unroll
        for (int o = 1; o <= 2; o <<= 1) {
            mx0 = fmaxf(mx0, __shfl_xor_sync(0xffffffffu, mx0, o));
            mx1 = fmaxf(mx1, __shfl_xor_sync(0xffffffffu, mx1, o));
        }
        float mn0 = fmaxf(mrow[0], mx0);
        float mn1 = fmaxf(mrow[1], mx1);
        float cr0 = ex2f(mrow[0] - mn0);
        float cr1 = ex2f(mrow[1] - mn1);
        lrow[0] *= cr0; lrow[1] *= cr1;
        mrow[0] = mn0;  mrow[1] = mn1;
        #pragma unroll
        for (int j = 0; j < 8; j++) {
            O[j][0] *= cr0; O[j][1] *= cr0; O[j][2] *= cr1; O[j][3] *= cr1;
        }

        // exp2 + A-fragment packing (register-only; C-frag pair -> A-frag)
        uint32_t Pa[4][4];
        float ps0 = 0.f, ps1 = 0.f;
        #pragma unroll
        for (int kk = 0; kk < 4; kk++) {
            #pragma unroll
            for (int jj = 0; jj < 2; jj++) {
                int j = 2 * kk + jj;
                float p0 = ex2f(S[j][0] - mn0);
                float p1 = ex2f(S[j][1] - mn0);
                float p2 = ex2f(S[j][2] - mn1);
                float p3 = ex2f(S[j][3] - mn1);
                ps0 += p0 + p1; ps1 += p2 + p3;
                Pa[kk][2*jj]     = h2u(__floats2half2_rn(p0, p1));
                Pa[kk][2*jj + 1] = h2u(__floats2half2_rn(p2, p3));
            }
        }
        lrow[0] += ps0; lrow[1] += ps1;

        // ---- O += P @ V  (V b-frags via ldmatrix.trans) ----
        #pragma unroll
        for (int jdp = 0; jdp < 4; jdp++) {
            #pragma unroll
            for (int kk = 0; kk < 4; kk++) {
                uint32_t vb4[4];
                ldsm_x4_t(vb4, sV + (uint32_t)((kk * 16 + ((lane >> 3) & 1) * 8 + (lane & 7)) * AST
                                               + jdp * 16 + ((lane >> 4) & 1) * 8) * 2);
                mma_f16(O[2*jdp],     Pa[kk], vb4);
                mma_f16(O[2*jdp + 1], Pa[kk], vb4 + 2);
            }
        }

        issueKV(kt + 2);       // writes buf (kt+2)%3 == (kt-1)%3 — safe
    }

    // ---- finalize ----
    float l0 = lrow[0], l1 = lrow[1];
    #pragma unroll
    for (int o = 1; o <= 2; o <<= 1) {
        l0 += __shfl_xor_sync(0xffffffffu, l0, o);
        l1 += __shfl_xor_sync(0xffffffffu, l1, o);
    }
    float inv0 = 1.f / l0, inv1 = 1.f / l1;
    int b = bh >> 4, h = bh & 15;
    int r0 = qt * 128 + qr + g;
    int r1 = r0 + 8;
    #pragma unroll
    for (int j = 0; j < 8; j++) {
        int c = h * TD + 8 * j + 2 * t;
        *reinterpret_cast<__half2*>(out + (size_t)(b * TT + r0) * TC + c) =
            __floats2half2_rn(O[j][0] * inv0, O[j][1] * inv0);
        *reinterpret_cast<__half2*>(out + (size_t)(b * TT + r1) * TC + c) =
            __floats2half2_rn(O[j][2] * inv1, O[j][3] * inv1);
    }
}

// ---------------------------------------------------------------------------
// Launch
// ---------------------------------------------------------------------------
extern "C" void kernel_launch(void* const* d_in, const int* in_sizes, int n_in,
                              void* d_out, int out_size)
{
    const float* x           = (const float*)d_in[0];
    const float* ln1_g       = (const float*)d_in[1];
    const float* ln1_b       = (const float*)d_in[2];
    const float* w_qkv       = (const float*)d_in[3];
    const float* b_qkv       = (const float*)d_in[4];
    const float* w_attn_proj = (const float*)d_in[5];
    const float* b_attn_proj = (const float*)d_in[6];
    const float* ln2_g       = (const float*)d_in[7];
    const float* ln2_b       = (const float*)d_in[8];
    const float* w_fc        = (const float*)d_in[9];
    const float* b_fc        = (const float*)d_in[10];
    const float* w_out       = (const float*)d_in[11];
    const float* b_out       = (const float*)d_in[12];

    __half *h1, *qh, *kh, *vh, *att, *h2, *fc, *wqkvH, *wapH, *wfcH, *woutH;
    float *x1;
    cudaGetSymbolAddress((void**)&h1,    g_h1);
    cudaGetSymbolAddress((void**)&qh,    g_q);
    cudaGetSymbolAddress((void**)&kh,    g_k);
    cudaGetSymbolAddress((void**)&vh,    g_v);
    cudaGetSymbolAddress((void**)&att,   g_att);
    cudaGetSymbolAddress((void**)&x1,    g_x1);
    cudaGetSymbolAddress((void**)&h2,    g_h2);
    cudaGetSymbolAddress((void**)&fc,    g_fc);
    cudaGetSymbolAddress((void**)&wqkvH, g_wqkvH);
    cudaGetSymbolAddress((void**)&wapH,  g_wapH);
    cudaGetSymbolAddress((void**)&wfcH,  g_wfcH);
    cudaGetSymbolAddress((void**)&woutH, g_woutH);

    cudaFuncSetAttribute(hgemm<0, float>,  cudaFuncAttributeMaxDynamicSharedMemorySize, G_SMEM);
    cudaFuncSetAttribute(hgemm<1, __half>, cudaFuncAttributeMaxDynamicSharedMemorySize, G_SMEM);
    cudaFuncSetAttribute(hgemm<2, float>,  cudaFuncAttributeMaxDynamicSharedMemorySize, G_SMEM);
    cudaFuncSetAttribute(hgemm<3, float>,  cudaFuncAttributeMaxDynamicSharedMemorySize, G_SMEM);
    cudaFuncSetAttribute(attn_kernel,      cudaFuncAttributeMaxDynamicSharedMemorySize, ATT_SMEM);

    // 0) fp16 copies of all weights, one launch
    convert_all_kernel<<<(CVT_TOT / 8 + 255) / 256, 256>>>(
        w_qkv, w_attn_proj, w_fc, w_out, wqkvH, wapH, wfcH, woutH);

    // 1) ln1(x) -> fp16
    layernorm_kernel<<<TM_, 256>>>(x, ln1_g, ln1_b, h1);
    // 2) qkv GEMM, epilogue scatters Q(scaled, log2e-folded)/K/V head-major fp16
    hgemm<3, float><<<dim3(C3 / 128, TM_ / 128), 256, G_SMEM>>>(
        h1, wqkvH, b_qkv, nullptr, (float*)nullptr, qh, kh, vh, TM_, C3, TC);
    // 3) causal flash attention (fp16 tensor, log2 softmax) -> fp16
    attn_kernel<<<dim3(TT / 128, BH), 256, ATT_SMEM>>>(qh, kh, vh, att);
    // 4) x1 = x + att @ w_attn_proj + b
    hgemm<2, float><<<dim3(TC / 128, TM_ / 128), 256, G_SMEM>>>(
        att, wapH, b_attn_proj, x, x1, nullptr, nullptr, nullptr, TM_, TC, TC);
    // 5) ln2(x1) -> fp16
    layernorm_kernel<<<TM_, 256>>>(x1, ln2_g, ln2_b, h2);
    // 6) fc = gelu(h2 @ w_fc + b_fc) -> fp16
    hgemm<1, __half><<<dim3(C4 / 128, TM_ / 128), 256, G_SMEM>>>(
        h2, wfcH, b_fc, nullptr, fc, nullptr, nullptr, nullptr, TM_, C4, TC);
    // 7) out = x1 + fc @ w_out + b_out
    hgemm<2, float><<<dim3(TC / 128, TM_ / 128), 256, G_SMEM>>>(
        fc, woutH, b_out, x1, (float*)d_out, nullptr, nullptr, nullptr, TM_, TC, C4);
}

// round 15
// speedup vs baseline: 1.0105x; 1.0105x over previous
#include <cuda_runtime.h>
#include <cuda_fp16.h>
#include <math.h>
#include <stdint.h>

// Problem constants: B=2, T=2048, C=1024, H=16, D=64
#define TB   2
#define TT   2048
#define TC   1024
#define TH   16
#define TD   64
#define TM_  (TB*TT)          // 4096 rows total
#define C3   (3*TC)           // 3072
#define C4   (4*TC)           // 4096
#define BH   (TB*TH)          // 32

// ---------------------------------------------------------------------------
// Scratch (no allocations allowed -> __device__ globals)
// ---------------------------------------------------------------------------
__device__ __half g_h1  [TM_ * TC];       // ln1(x)              fp16
__device__ __half g_q   [BH * TT * TD];   // Q (scaled, log2e-folded) fp16 head-major
__device__ __half g_k   [BH * TT * TD];   // K                   fp16 head-major
__device__ __half g_v   [BH * TT * TD];   // V                   fp16 head-major
__device__ __half g_att [TM_ * TC];       // attention output    fp16
__device__ float  g_x1  [TM_ * TC];       // x + attn_proj       fp32
__device__ __half g_h2  [TM_ * TC];       // ln2(x1)             fp16
__device__ __half g_fc  [TM_ * C4];       // gelu(fc)            fp16
// fp16 copies of weights, SAME layout as input ([K][N] row-major)
__device__ __half g_wqkvH[TC * C3];
__device__ __half g_wapH [TC * TC];
__device__ __half g_wfcH [TC * C4];
__device__ __half g_woutH[C4 * TC];

// ---------------------------------------------------------------------------
// Helpers
// ---------------------------------------------------------------------------
__device__ __forceinline__ uint32_t h2u(__half2 h) {
    union { __half2 h; uint32_t u; } c;
    c.h = h;
    return c.u;
}
__device__ __forceinline__ float ex2f(float x) {   // 2^x, single MUFU op
    float r;
    asm("ex2.approx.ftz.f32 %0, %1;" : "=f"(r) : "f"(x));
    return r;
}
__device__ __forceinline__ uint32_t smem_u32(const void* p) {
    uint32_t a;
    asm("{ .reg .u64 t; cvta.to.shared.u64 t, %1; cvt.u32.u64 %0, t; }"
        : "=r"(a) : "l"(p));
    return a;
}
__device__ __forceinline__ void cp_async16(uint32_t dst, const void* src) {
    asm volatile("cp.async.cg.shared.global [%0], [%1], 16;"
                 :: "r"(dst), "l"(src) : "memory");
}
#define CP_COMMIT() asm volatile("cp.async.commit_group;" ::: "memory")
#define CP_WAIT1()  asm volatile("cp.async.wait_group 1;" ::: "memory")

__device__ __forceinline__ void mma_f16(float* d, const uint32_t* a, const uint32_t* b) {
    asm volatile(
        "mma.sync.aligned.m16n8k16.row.col.f32.f16.f16.f32 "
        "{%0,%1,%2,%3}, {%4,%5,%6,%7}, {%8,%9}, {%0,%1,%2,%3};"
        : "+f"(d[0]), "+f"(d[1]), "+f"(d[2]), "+f"(d[3])
        : "r"(a[0]), "r"(a[1]), "r"(a[2]), "r"(a[3]), "r"(b[0]), "r"(b[1]));
}
__device__ __forceinline__ void ldsm_x4(uint32_t* r, uint32_t addr) {
    asm volatile("ldmatrix.sync.aligned.m8n8.x4.shared.b16 {%0,%1,%2,%3}, [%4];"
                 : "=r"(r[0]), "=r"(r[1]), "=r"(r[2]), "=r"(r[3]) : "r"(addr));
}
__device__ __forceinline__ void ldsm_x4_t(uint32_t* r, uint32_t addr) {
    asm volatile("ldmatrix.sync.aligned.m8n8.x4.trans.shared.b16 {%0,%1,%2,%3}, [%4];"
                 : "=r"(r[0]), "=r"(r[1]), "=r"(r[2]), "=r"(r[3]) : "r"(addr));
}

// ---------------------------------------------------------------------------
// Block reduce (for LayerNorm)
// ---------------------------------------------------------------------------
__device__ __forceinline__ float blockReduceSum(float v) {
    __shared__ float sh[32];
    int lane = threadIdx.x & 31;
    #pragma unroll
    for (int o = 16; o > 0; o >>= 1) v += __shfl_xor_sync(0xffffffffu, v, o);
    __syncthreads();
    if (lane == 0) sh[threadIdx.x >> 5] = v;
    __syncthreads();
    float t = (lane < 8) ? sh[lane] : 0.f;
    #pragma unroll
    for (int o = 4; o > 0; o <<= 0, o >>= 1) t += __shfl_xor_sync(0xffffffffu, t, o);
    return __shfl_sync(0xffffffffu, t, 0);
}

// ---------------------------------------------------------------------------
// LayerNorm row body -> fp16
// ---------------------------------------------------------------------------
__device__ __forceinline__ void ln_row(
    const float* __restrict__ x, const float* __restrict__ g,
    const float* __restrict__ b, __half* __restrict__ out, int row)
{
    const float4* xr = reinterpret_cast<const float4*>(x + (size_t)row * TC);
    float4 v = xr[threadIdx.x];
    float mean = blockReduceSum(v.x + v.y + v.z + v.w) * (1.f / TC);
    float dx = v.x - mean, dy = v.y - mean, dz = v.z - mean, dw = v.w - mean;
    float var = blockReduceSum(dx*dx + dy*dy + dz*dz + dw*dw) * (1.f / TC);
    float rstd = rsqrtf(var + 1e-5f);
    float4 gv = reinterpret_cast<const float4*>(g)[threadIdx.x];
    float4 bv = reinterpret_cast<const float4*>(b)[threadIdx.x];
    __half2* o2 = reinterpret_cast<__half2*>(out + (size_t)row * TC);
    o2[2 * threadIdx.x]     = __floats2half2_rn(dx * rstd * gv.x + bv.x, dy * rstd * gv.y + bv.y);
    o2[2 * threadIdx.x + 1] = __floats2half2_rn(dz * rstd * gv.z + bv.z, dw * rstd * gv.w + bv.w);
}

__global__ __launch_bounds__(256) void layernorm_kernel(
    const float* __restrict__ x, const float* __restrict__ g,
    const float* __restrict__ b, __half* __restrict__ out)
{
    ln_row(x, g, b, out, blockIdx.x);
}

// ---------------------------------------------------------------------------
// Fused prep: LN1 (blocks [0, TM_)) + fp32->fp16 weight convert (rest).
// ---------------------------------------------------------------------------
#define CVT_N1 (TC * C3)
#define CVT_N2 (TC * TC)
#define CVT_N3 (TC * C4)
#define CVT_N4 (C4 * TC)
#define CVT_TOT (CVT_N1 + CVT_N2 + CVT_N3 + CVT_N4)
#define CVT_BLOCKS ((CVT_TOT / 8 + 255) / 256)

__global__ __launch_bounds__(256) void prep_kernel(
    const float* __restrict__ x, const float* __restrict__ ln_g,
    const float* __restrict__ ln_b, __half* __restrict__ h1,
    const float* __restrict__ w1, const float* __restrict__ w2,
    const float* __restrict__ w3, const float* __restrict__ w4,
    __half* __restrict__ o1, __half* __restrict__ o2,
    __half* __restrict__ o3, __half* __restrict__ o4)
{
    if (blockIdx.x < TM_) {
        ln_row(x, ln_g, ln_b, h1, blockIdx.x);
        return;
    }
    int i = ((blockIdx.x - TM_) * 256 + threadIdx.x) * 8;
    if (i >= CVT_TOT) return;
    const float* W;
    __half* Wh;
    if (i < CVT_N1)                       { W = w1;  Wh = o1;  }
    else if (i < CVT_N1 + CVT_N2)         { W = w2 - CVT_N1;           Wh = o2 - CVT_N1; }
    else if (i < CVT_N1 + CVT_N2 + CVT_N3){ W = w3 - CVT_N1 - CVT_N2;  Wh = o3 - CVT_N1 - CVT_N2; }
    else                                  { W = w4 - CVT_N1 - CVT_N2 - CVT_N3; Wh = o4 - CVT_N1 - CVT_N2 - CVT_N3; }
    float4 a = *reinterpret_cast<const float4*>(W + i);
    float4 b = *reinterpret_cast<const float4*>(W + i + 4);
    __half2 h[4];
    h[0] = __floats2half2_rn(a.x, a.y);
    h[1] = __floats2half2_rn(a.z, a.w);
    h[2] = __floats2half2_rn(b.x, b.y);
    h[3] = __floats2half2_rn(b.z, b.w);
    *reinterpret_cast<uint4*>(Wh + i) = *reinterpret_cast<uint4*>(h);
}

// ---------------------------------------------------------------------------
// fp16 tensor GEMM (at legacy-HMMA ceiling — do not touch)
// BM=128, BN=128, BK=64. 256 threads = 8 warps (4m x 2n); warp tile 32x64.
// ---------------------------------------------------------------------------
#define A_BYTES   (128 * 144)
#define B_BYTES   (64 * 272)
#define STG_BYTES (A_BYTES + B_BYTES)    // 35840
#define GNST      3
#define G_SMEM    (GNST * STG_BYTES)     // 107520

template <int EPI, typename OutT>
__global__ __launch_bounds__(256) void hgemm(
    const __half* __restrict__ A, const __half* __restrict__ W,
    const float* __restrict__ bias, const float* __restrict__ res,
    OutT* __restrict__ C,
    __half* __restrict__ qh, __half* __restrict__ kh, __half* __restrict__ vh,
    int M, int N, int K)
{
    extern __shared__ __half shh[];
    uint32_t sbase = smem_u32(shh);

    int tid  = threadIdx.x;
    int wid  = tid >> 5;
    int lane = tid & 31;
    int g    = lane >> 2;
    int t    = lane & 3;
    int brow = blockIdx.y * 128;
    int bcol = blockIdx.x * 128;
    int m0   = (wid >> 1) * 32;
    int n0   = (wid & 1) * 64;

    const __half* Ag = A + (size_t)brow * K;

    int NC = K >> 6;

    auto issue = [&](int kc) {
        if (kc < NC) {
            int k0 = kc << 6;
            uint32_t abuf = sbase + (uint32_t)(kc % GNST) * STG_BYTES;
            uint32_t bbuf = abuf + A_BYTES;
            #pragma unroll
            for (int i = 0; i < 4; i++) {               // A: 1024 x 16B
                int idx = tid + (i << 8);
                int row = idx >> 3;
                int c   = idx & 7;
                cp_async16(abuf + (uint32_t)(row * 144 + c * 16),
                           Ag + (size_t)row * K + k0 + c * 8);
            }
            #pragma unroll
            for (int i = 0; i < 4; i++) {               // B: 1024 x 16B
                int idx = tid + (i << 8);
                int row = idx >> 4;
                int c   = idx & 15;
                cp_async16(bbuf + (uint32_t)(row * 272 + c * 16),
                           W + (size_t)(k0 + row) * N + bcol + c * 8);
            }
        }
        CP_COMMIT();
    };

    float acc[2][8][4];
    #pragma unroll
    for (int i = 0; i < 2; i++)
        #pragma unroll
        for (int j = 0; j < 8; j++)
            #pragma unroll
            for (int q = 0; q < 4; q++) acc[i][j][q] = 0.f;

    issue(0);
    issue(1);

    int a_r = lane & 15;
    int a_c = (lane >> 4) * 16;
    int b_tr = ((lane >> 3) & 1) * 8 + (lane & 7);
    int b_tc = ((lane >> 4) & 1) * 16;

    for (int kc = 0; kc < NC; kc++) {
        CP_WAIT1();
        __syncthreads();
        issue(kc + 2);

        uint32_t As = sbase + (uint32_t)(kc % GNST) * STG_BYTES;
        uint32_t Bs = As + A_BYTES;

        #pragma unroll
        for (int ks = 0; ks < 4; ks++) {
            uint32_t a[2][4];
            #pragma unroll
            for (int i = 0; i < 2; i++)
                ldsm_x4(a[i], As + (uint32_t)((m0 + i * 16 + a_r) * 144 + ks * 32 + a_c));
            uint32_t b[4][4];
            #pragma unroll
            for (int jp = 0; jp < 4; jp++)
                ldsm_x4_t(b[jp], Bs + (uint32_t)((ks * 16 + b_tr) * 272
                                                 + n0 * 2 + jp * 32 + b_tc));
            #pragma unroll
            for (int i = 0; i < 2; i++)
                #pragma unroll
                for (int j = 0; j < 8; j++)
                    mma_f16(acc[i][j], a[i], b[j >> 1] + (j & 1) * 2);
        }
    }

    // ---- epilogue ----
    #pragma unroll
    for (int i = 0; i < 2; i++) {
        int r0 = brow + m0 + i * 16 + g;
        int r1 = r0 + 8;
        #pragma unroll
        for (int j = 0; j < 8; j++) {
            int c0 = bcol + n0 + j * 8 + 2 * t;
            float bx = bias[c0], by = bias[c0 + 1];
            float v0 = acc[i][j][0] + bx;
            float v1 = acc[i][j][1] + by;
            float v2 = acc[i][j][2] + bx;
            float v3 = acc[i][j][3] + by;
            if (EPI == 1) {
                v0 = 0.5f * v0 * (1.0f + erff(v0 * 0.70710678118654752440f));
                v1 = 0.5f * v1 * (1.0f + erff(v1 * 0.70710678118654752440f));
                v2 = 0.5f * v2 * (1.0f + erff(v2 * 0.70710678118654752440f));
                v3 = 0.5f * v3 * (1.0f + erff(v3 * 0.70710678118654752440f));
            } else if (EPI == 2) {
                const float2 ra = *reinterpret_cast<const float2*>(res + (size_t)r0 * N + c0);
                const float2 rb = *reinterpret_cast<const float2*>(res + (size_t)r1 * N + c0);
                v0 += ra.x; v1 += ra.y; v2 += rb.x; v3 += rb.y;
            }
            if (EPI == 3) {
                // scatter into head-major Q/K/V.
                // Q scale folds C^-0.5 AND log2(e): softmax runs in log2 domain.
                int which = c0 >> 10;
                int cc = c0 & 1023;
                int hh = cc >> 6, d = cc & 63;
                __half* base = (which == 0) ? qh : ((which == 1) ? kh : vh);
                float s = (which == 0) ? 0.045084220027780106f : 1.0f; // 2^-5 * log2(e)
                int b0i = r0 >> 11, t0i = r0 & 2047;
                int b1i = r1 >> 11, t1i = r1 & 2047;
                *reinterpret_cast<__half2*>(base + ((size_t)((b0i * TH + hh) * TT + t0i) * TD + d)) =
                    __floats2half2_rn(v0 * s, v1 * s);
                *reinterpret_cast<__half2*>(base + ((size_t)((b1i * TH + hh) * TT + t1i) * TD + d)) =
                    __floats2half2_rn(v2 * s, v3 * s);
            } else if constexpr (sizeof(OutT) == 2) {
                *reinterpret_cast<__half2*>((__half*)C + (size_t)r0 * N + c0) = __floats2half2_rn(v0, v1);
                *reinterpret_cast<__half2*>((__half*)C + (size_t)r1 * N + c0) = __floats2half2_rn(v2, v3);
            } else {
                *reinterpret_cast<float2*>((float*)C + (size_t)r0 * N + c0) = make_float2(v0, v1);
                *reinterpret_cast<float2*>((float*)C + (size_t)r1 * N + c0) = make_float2(v2, v3);
            }
        }
    }
}

// ---------------------------------------------------------------------------
// Causal flash attention — R13 loop (3 KV buffers, ONE sync/tile), persistent
// Qa, plus BIT-EXACT masked-work skipping:
//  * at kt == 2qt+1, warps with qr <= 48 are fully masked (p == 0 exactly);
//    they skip S/softmax/PV but keep the barrier/issue protocol.
//  * mask pass only runs for warps that can actually straddle the diagonal.
// ---------------------------------------------------------------------------
#define AST    72
#define QS_H   (128 * AST)      // 9216 halfs
#define KS_H   (64 * AST)       // 4608 halfs
#define ATT_SMEM ((QS_H + 6 * KS_H) * 2)  // 73728 bytes

__global__ __launch_bounds__(256) void attn_kernel(
    const __half* __restrict__ Qh, const __half* __restrict__ Kh,
    const __half* __restrict__ Vh, __half* __restrict__ out)
{
    extern __shared__ __half ash[];
    __half* Qs  = ash;
    __half* KsB = ash + QS_H;            // 3 x KS_H
    __half* VsB = ash + QS_H + 3 * KS_H; // 3 x KS_H

    int qt  = gridDim.x - 1 - blockIdx.x;   // heavy (large-qt) CTAs first
    int bh  = blockIdx.y;                   // b*16 + h
    int tid = threadIdx.x;
    int wid = tid >> 5;
    int lane = tid & 31;
    int g = lane >> 2;
    int t = lane & 3;
    int qr = wid * 16;                   // local q row base (0..112)

    // ---- stage Q supertile (128 x 64, pre-scaled fp16) ----
    const __half* qbase = Qh + ((size_t)bh * TT + qt * 128) * TD;
    #pragma unroll
    for (int i = 0; i < 4; i++) {
        int idx = tid + (i << 8);            // 0..1023
        int r = idx >> 3, c = idx & 7;
        *reinterpret_cast<uint4*>(Qs + r * AST + c * 8) =
            *reinterpret_cast<const uint4*>(qbase + r * TD + c * 8);
    }
    __syncthreads();

    uint32_t sQ = smem_u32(Qs);
    uint32_t Qa[4][4];
    #pragma unroll
    for (int ks = 0; ks < 4; ks++)
        ldsm_x4(Qa[ks], sQ + (uint32_t)((qr + (lane & 15)) * AST + ks * 16 + (lane >> 4) * 8) * 2);

    float O[8][4];
    #pragma unroll
    for (int j = 0; j < 8; j++)
        #pragma unroll
        for (int q = 0; q < 4; q++) O[j][q] = 0.f;
    float mrow[2] = {-1e30f, -1e30f};
    float lrow[2] = {0.f, 0.f};

    int ktmax = 2 * qt + 1;              // last kv tile index

    auto issueKV = [&](int kt) {
        if (kt <= ktmax) {
            const __half* kbase = Kh + ((size_t)bh * TT + kt * 64) * TD;
            const __half* vbase = Vh + ((size_t)bh * TT + kt * 64) * TD;
            uint32_t kb = smem_u32(KsB + (kt % 3) * KS_H);
            uint32_t vb = smem_u32(VsB + (kt % 3) * KS_H);
            #pragma unroll
            for (int i = 0; i < 2; i++) {
                int idx = tid + (i << 8);    // 0..511
                int r = idx >> 3, c = idx & 7;
                uint32_t so = (uint32_t)(r * AST + c * 8) * 2;
                cp_async16(kb + so, kbase + r * TD + c * 8);
                cp_async16(vb + so, vbase + r * TD + c * 8);
            }
        }
        CP_COMMIT();
    };

    issueKV(0);
    issueKV(1);

    for (int kt = 0; kt <= ktmax; kt++) {
        CP_WAIT1();            // tile kt resident (only kt+1 may be pending)
        __syncthreads();       // + all warps done with iter kt-1 reads

        // Fully-masked warps at the final half-tile contribute exactly 0:
        // skip all compute (p = ex2(-1e30 - mn) == 0, corr == 1).
        bool active = !(kt == 2 * qt + 1 && qr <= 48);

        if (active) {
            uint32_t sK = smem_u32(KsB + (kt % 3) * KS_H);
            uint32_t sV = smem_u32(VsB + (kt % 3) * KS_H);

            // ---- S = Q @ K^T  (log2-domain logits) ----
            float S[8][4];
            #pragma unroll
            for (int jp = 0; jp < 4; jp++) {
                #pragma unroll
                for (int q = 0; q < 4; q++) { S[2*jp][q] = 0.f; S[2*jp+1][q] = 0.f; }
                #pragma unroll
                for (int ks = 0; ks < 4; ks++) {
                    uint32_t kb4[4];
                    ldsm_x4(kb4, sK + (uint32_t)((jp * 16 + ((lane >> 4) & 1) * 8 + (lane & 7)) * AST
                                                 + ks * 16 + ((lane >> 3) & 1) * 8) * 2);
                    mma_f16(S[2*jp],     Qa[ks], kb4);
                    mma_f16(S[2*jp + 1], Qa[ks], kb4 + 2);
                }
            }

            // ---- causal mask (only warps that straddle the diagonal) ----
            if (kt >= 2 * qt) {
                int off = (kt - 2 * qt) * 64;
                if (off + 63 > qr) {
                    int r0 = qr + g, r1 = r0 + 8;
                    #pragma unroll
                    for (int j = 0; j < 8; j++) {
                        int c0 = off + 8 * j + 2 * t, c1 = c0 + 1;
                        if (c0 > r0) S[j][0] = -1e30f;
                        if (c1 > r0) S[j][1] = -1e30f;
                        if (c0 > r1) S[j][2] = -1e30f;
                        if (c1 > r1) S[j][3] = -1e30f;
                    }
                }
            }

            // ---- online softmax (base 2) ----
            float mx0 = -1e30f, mx1 = -1e30f;
            #pragma unroll
            for (int j = 0; j < 8; j++) {
                mx0 = fmaxf(mx0, fmaxf(S[j][0], S[j][1]));
                mx1 = fmaxf(mx1, fmaxf(S[j][2], S[j][3]));
            }
            #pragma unroll
            for (int o = 1; o <= 2; o <<= 1) {
                mx0 = fmaxf(mx0, __shfl_xor_sync(0xffffffffu, mx0, o));
                mx1 = fmaxf(mx1, __shfl_xor_sync(0xffffffffu, mx1, o));
            }
            float mn0 = fmaxf(mrow[0], mx0);
            float mn1 = fmaxf(mrow[1], mx1);
            float cr0 = ex2f(mrow[0] - mn0);
            float cr1 = ex2f(mrow[1] - mn1);
            lrow[0] *= cr0; lrow[1] *= cr1;
            mrow[0] = mn0;  mrow[1] = mn1;
            #pragma unroll
            for (int j = 0; j < 8; j++) {
                O[j][0] *= cr0; O[j][1] *= cr0; O[j][2] *= cr1; O[j][3] *= cr1;
            }

            // exp2 + A-fragment packing (register-only; C-frag pair -> A-frag)
            uint32_t Pa[4][4];
            float ps0 = 0.f, ps1 = 0.f;
            #pragma unroll
            for (int kk = 0; kk < 4; kk++) {
                #pragma unroll
                for (int jj = 0; jj < 2; jj++) {
                    int j = 2 * kk + jj;
                    float p0 = ex2f(S[j][0] - mn0);
                    float p1 = ex2f(S[j][1] - mn0);
                    float p2 = ex2f(S[j][2] - mn1);
                    float p3 = ex2f(S[j][3] - mn1);
                    ps0 += p0 + p1; ps1 += p2 + p3;
                    Pa[kk][2*jj]     = h2u(__floats2half2_rn(p0, p1));
                    Pa[kk][2*jj + 1] = h2u(__floats2half2_rn(p2, p3));
                }
            }
            lrow[0] += ps0; lrow[1] += ps1;

            // ---- O += P @ V  (V b-frags via ldmatrix.trans) ----
            #pragma unroll
            for (int jdp = 0; jdp < 4; jdp++) {
                #pragma unroll
                for (int kk = 0; kk < 4; kk++) {
                    uint32_t vb4[4];
                    ldsm_x4_t(vb4, sV + (uint32_t)((kk * 16 + ((lane >> 3) & 1) * 8 + (lane & 7)) * AST
                                                   + jdp * 16 + ((lane >> 4) & 1) * 8) * 2);
                    mma_f16(O[2*jdp],     Pa[kk], vb4);
                    mma_f16(O[2*jdp + 1], Pa[kk], vb4 + 2);
                }
            }
        }

        issueKV(kt + 2);       // writes buf (kt+2)%3 == (kt-1)%3 — safe
    }

    // ---- finalize ----
    float l0 = lrow[0], l1 = lrow[1];
    #pragma unroll
    for (int o = 1; o <= 2; o <<= 1) {
        l0 += __shfl_xor_sync(0xffffffffu, l0, o);
        l1 += __shfl_xor_sync(0xffffffffu, l1, o);
    }
    float inv0 = 1.f / l0, inv1 = 1.f / l1;
    int b = bh >> 4, h = bh & 15;
    int r0 = qt * 128 + qr + g;
    int r1 = r0 + 8;
    #pragma unroll
    for (int j = 0; j < 8; j++) {
        int c = h * TD + 8 * j + 2 * t;
        *reinterpret_cast<__half2*>(out + (size_t)(b * TT + r0) * TC + c) =
            __floats2half2_rn(O[j][0] * inv0, O[j][1] * inv0);
        *reinterpret_cast<__half2*>(out + (size_t)(b * TT + r1) * TC + c) =
            __floats2half2_rn(O[j][2] * inv1, O[j][3] * inv1);
    }
}

// ---------------------------------------------------------------------------
// Launch
// ---------------------------------------------------------------------------
extern "C" void kernel_launch(void* const* d_in, const int* in_sizes, int n_in,
                              void* d_out, int out_size)
{
    const float* x           = (const float*)d_in[0];
    const float* ln1_g       = (const float*)d_in[1];
    const float* ln1_b       = (const float*)d_in[2];
    const float* w_qkv       = (const float*)d_in[3];
    const float* b_qkv       = (const float*)d_in[4];
    const float* w_attn_proj = (const float*)d_in[5];
    const float* b_attn_proj = (const float*)d_in[6];
    const float* ln2_g       = (const float*)d_in[7];
    const float* ln2_b       = (const float*)d_in[8];
    const float* w_fc        = (const float*)d_in[9];
    const float* b_fc        = (const float*)d_in[10];
    const float* w_out       = (const float*)d_in[11];
    const float* b_out       = (const float*)d_in[12];

    __half *h1, *qh, *kh, *vh, *att, *h2, *fc, *wqkvH, *wapH, *wfcH, *woutH;
    float *x1;
    cudaGetSymbolAddress((void**)&h1,    g_h1);
    cudaGetSymbolAddress((void**)&qh,    g_q);
    cudaGetSymbolAddress((void**)&kh,    g_k);
    cudaGetSymbolAddress((void**)&vh,    g_v);
    cudaGetSymbolAddress((void**)&att,   g_att);
    cudaGetSymbolAddress((void**)&x1,    g_x1);
    cudaGetSymbolAddress((void**)&h2,    g_h2);
    cudaGetSymbolAddress((void**)&fc,    g_fc);
    cudaGetSymbolAddress((void**)&wqkvH, g_wqkvH);
    cudaGetSymbolAddress((void**)&wapH,  g_wapH);
    cudaGetSymbolAddress((void**)&wfcH,  g_wfcH);
    cudaGetSymbolAddress((void**)&woutH, g_woutH);

    cudaFuncSetAttribute(hgemm<0, float>,  cudaFuncAttributeMaxDynamicSharedMemorySize, G_SMEM);
    cudaFuncSetAttribute(hgemm<1, __half>, cudaFuncAttributeMaxDynamicSharedMemorySize, G_SMEM);
    cudaFuncSetAttribute(hgemm<2, float>,  cudaFuncAttributeMaxDynamicSharedMemorySize, G_SMEM);
    cudaFuncSetAttribute(hgemm<3, float>,  cudaFuncAttributeMaxDynamicSharedMemorySize, G_SMEM);
    cudaFuncSetAttribute(attn_kernel,      cudaFuncAttributeMaxDynamicSharedMemorySize, ATT_SMEM);

    // 0) fused: ln1(x) -> fp16 AND fp16 copies of all weights, one launch
    prep_kernel<<<TM_ + CVT_BLOCKS, 256>>>(
        x, ln1_g, ln1_b, h1,
        w_qkv, w_attn_proj, w_fc, w_out, wqkvH, wapH, wfcH, woutH);

    // 1) qkv GEMM, epilogue scatters Q(scaled, log2e-folded)/K/V head-major fp16
    hgemm<3, float><<<dim3(C3 / 128, TM_ / 128), 256, G_SMEM>>>(
        h1, wqkvH, b_qkv, nullptr, (float*)nullptr, qh, kh, vh, TM_, C3, TC);
    // 2) causal flash attention (fp16 tensor, log2 softmax) -> fp16
    attn_kernel<<<dim3(TT / 128, BH), 256, ATT_SMEM>>>(qh, kh, vh, att);
    // 3) x1 = x + att @ w_attn_proj + b
    hgemm<2, float><<<dim3(TC / 128, TM_ / 128), 256, G_SMEM>>>(
        att, wapH, b_attn_proj, x, x1, nullptr, nullptr, nullptr, TM_, TC, TC);
    // 4) ln2(x1) -> fp16
    layernorm_kernel<<<TM_, 256>>>(x1, ln2_g, ln2_b, h2);
    // 5) fc = gelu(h2 @ w_fc + b_fc) -> fp16
    hgemm<1, __half><<<dim3(C4 / 128, TM_ / 128), 256, G_SMEM>>>(
        h2, wfcH, b_fc, nullptr, fc, nullptr, nullptr, nullptr, TM_, C4, TC);
    // 6) out = x1 + fc @ w_out + b_out
    hgemm<2, float><<<dim3(TC / 128, TM_ / 128), 256, G_SMEM>>>(
        fc, woutH, b_out, x1, (float*)d_out, nullptr, nullptr, nullptr, TM_, TC, C4);
}